// round 8
// baseline (speedup 1.0000x reference)
#include <cuda_runtime.h>
#include <cuda_fp16.h>
#include <cstdint>

// out[8192,4096] = x[8192,4096] @ W[4096,4096]^T,  W = (q - zp)*scale
// fp16 HMMA (mma.sync.m16n8k16, fp32 accum). cp.async.bulk loads from
// prep-tiled pre-swizzled scratch; register ping-pong; BK=64; 16 warps
// (4 warps/SMSP) so TRYWAIT/LDSM phases of one warp hide under others' MMAs.
#define MDIM 8192
#define KDIM 4096
#define NDIM 4096

static constexpr int BM = 128, BN = 256, BK = 64;
static constexpr int A_BLK = BM * BK * 2;     // 16384 B per (m-tile, k-chunk)
static constexpr int B_BLK = BN * BK * 2;     // 32768 B
static constexpr int STAGE = A_BLK + B_BLK;   // 49152
static constexpr int ST = 4;
static constexpr int KT = KDIM / BK;          // 64
static constexpr int SMEM_TOTAL = 1024 + ST * STAGE;  // 197632
static constexpr int NWARP = 16;

// tiled+swizzled scratch: A: [64 mt][64 kt][16KB], B: [16 nt][64 kt][32KB]
// row r holds its 128B K-slice; 16B unit u at offset r*128 + (u^(r&7))*16.
__device__ uint4 g_xa[(size_t)MDIM * KDIM * 2 / 16];
__device__ uint4 g_wb[(size_t)NDIM * KDIM * 2 / 16];

__device__ __forceinline__ uint32_t smem_to_u32(const void* p) {
    uint32_t a;
    asm("{ .reg .u64 t; cvta.to.shared.u64 t, %1; cvt.u32.u64 %0, t; }"
        : "=r"(a) : "l"(p));
    return a;
}

#define MBARRIER_INIT(addr, cnt) \
    asm volatile("mbarrier.init.shared.b64 [%0], %1;" :: "r"((uint32_t)(addr)), "r"((uint32_t)(cnt)) : "memory")
#define MBARRIER_ARRIVE(addr) \
    asm volatile("mbarrier.arrive.shared.b64 _, [%0];" :: "r"((uint32_t)(addr)) : "memory")
#define MBARRIER_EXPECT_TX(addr, bytes) \
    asm volatile("mbarrier.arrive.expect_tx.shared.b64 _, [%0], %1;" :: "r"((uint32_t)(addr)), "r"((uint32_t)(bytes)) : "memory")
#define MBARRIER_WAIT_PARITY(mbar_smem_addr, phase_parity) do { \
    uint32_t _mbar = (uint32_t)(mbar_smem_addr); \
    uint32_t _parity = (uint32_t)(phase_parity); \
    uint32_t _done; \
    asm volatile( \
        "{\n\t.reg .pred p;\n\t" \
        "mbarrier.try_wait.parity.acquire.cta.shared::cta.b64 p, [%1], %2;\n\t" \
        "selp.b32 %0, 1, 0, p;\n\t}" \
        : "=r"(_done) : "r"(_mbar), "r"(_parity) : "memory"); \
    if (!_done) { \
        asm volatile( \
            "{\n\t.reg .pred P1;\n\t" \
            "WAIT_LOOP_%=:\n\t" \
            "mbarrier.try_wait.parity.acquire.cta.shared::cta.b64 P1, [%0], %1, 0x989680;\n\t" \
            "@P1 bra.uni WAIT_DONE_%=;\n\t" \
            "bra.uni WAIT_LOOP_%=;\n\t" \
            "WAIT_DONE_%=:\n\t}" \
            :: "r"(_mbar), "r"(_parity) : "memory"); \
    } \
} while(0)

#define BULK_G2S(dst, src, bytes, mbar) \
    asm volatile("cp.async.bulk.shared::cluster.global.mbarrier::complete_tx::bytes [%0], [%1], %2, [%3];" \
        :: "r"((uint32_t)(dst)), "l"(src), "r"((uint32_t)(bytes)), "r"((uint32_t)(mbar)) : "memory")

#define LDMATRIX_X4(r0, r1, r2, r3, addr) \
    asm volatile("ldmatrix.sync.aligned.m8n8.x4.shared.b16 {%0,%1,%2,%3}, [%4];" \
        : "=r"(r0), "=r"(r1), "=r"(r2), "=r"(r3) : "r"(addr))

#define MMA_16816(c, a0, a1, a2, a3, b0, b1) \
    asm volatile("mma.sync.aligned.m16n8k16.row.col.f32.f16.f16.f32 " \
        "{%0,%1,%2,%3}, {%4,%5,%6,%7}, {%8,%9}, {%0,%1,%2,%3};" \
        : "+f"((c)[0]), "+f"((c)[1]), "+f"((c)[2]), "+f"((c)[3]) \
        : "r"(a0), "r"(a1), "r"(a2), "r"(a3), "r"(b0), "r"(b1))

// ------------------------------- prep kernel -------------------------------
static constexpr int XBLKS = (int)(((size_t)MDIM * KDIM / 8) / 256);  // 16384
static constexpr int WBLKS = (int)(((size_t)NDIM * KDIM / 8) / 256);  // 8192

__global__ void __launch_bounds__(256) prep_kernel(const float* __restrict__ x,
                                                   const int* __restrict__ q,
                                                   const int* __restrict__ zp) {
    if (blockIdx.x < XBLKS) {
        size_t t = (size_t)blockIdx.x * blockDim.x + threadIdx.x;  // one 16B unit
        int m = (int)(t >> 9);
        int k = ((int)t & 511) * 8;
        const float4* src = reinterpret_cast<const float4*>(x + (size_t)m * KDIM + k);
        float4 v0 = src[0], v1 = src[1];
        __half2 h0 = __floats2half2_rn(v0.x, v0.y);
        __half2 h1 = __floats2half2_rn(v0.z, v0.w);
        __half2 h2 = __floats2half2_rn(v1.x, v1.y);
        __half2 h3 = __floats2half2_rn(v1.z, v1.w);
        uint4 o;
        o.x = *reinterpret_cast<uint32_t*>(&h0);
        o.y = *reinterpret_cast<uint32_t*>(&h1);
        o.z = *reinterpret_cast<uint32_t*>(&h2);
        o.w = *reinterpret_cast<uint32_t*>(&h3);
        int mt = m >> 7, r = m & 127, kt = k >> 6, kc8 = (k & 63) >> 3;
        uint32_t off = (uint32_t)r * 128 + (uint32_t)((kc8 ^ (r & 7)) * 16);
        g_xa[((size_t)(mt * KT + kt) * A_BLK + off) >> 4] = o;
    } else {
        int z = __ldg(zp);
        size_t t = (size_t)(blockIdx.x - XBLKS) * blockDim.x + threadIdx.x;
        int n = (int)(t >> 9);
        int k = ((int)t & 511) * 8;
        const int4* src = reinterpret_cast<const int4*>(q + (size_t)n * KDIM + k);
        int4 q0 = src[0], q1 = src[1];
        __half2 h0 = __floats2half2_rn((float)(q0.x - z), (float)(q0.y - z));
        __half2 h1 = __floats2half2_rn((float)(q0.z - z), (float)(q0.w - z));
        __half2 h2 = __floats2half2_rn((float)(q1.x - z), (float)(q1.y - z));
        __half2 h3 = __floats2half2_rn((float)(q1.z - z), (float)(q1.w - z));
        uint4 o;
        o.x = *reinterpret_cast<uint32_t*>(&h0);
        o.y = *reinterpret_cast<uint32_t*>(&h1);
        o.z = *reinterpret_cast<uint32_t*>(&h2);
        o.w = *reinterpret_cast<uint32_t*>(&h3);
        int nt = n >> 8, r = n & 255, kt = k >> 6, kc8 = (k & 63) >> 3;
        uint32_t off = (uint32_t)r * 128 + (uint32_t)((kc8 ^ (r & 7)) * 16);
        g_wb[((size_t)(nt * KT + kt) * B_BLK + off) >> 4] = o;
    }
}

// ------------------------------- GEMM --------------------------------------
// CTA 128x256, K-chunk 64. 16 warps: 4(M) x 4(N), warp tile 32x64.
__global__ void __launch_bounds__(512, 1)
gemm_kernel(const float* __restrict__ bias,
            const float* __restrict__ wscale,
            float* __restrict__ out) {
    extern __shared__ char smem[];
    const uint32_t sbase = smem_to_u32(smem);
    const int tid = threadIdx.x;
    const int lane = tid & 31;
    const int wid = tid >> 5;
    const int warp_m = wid & 3;        // 0..3  (32 rows each)
    const int warp_n = wid >> 2;       // 0..3  (64 cols each)

    // CTA swizzle: groups of 8 M-tiles sweep all 16 N-tiles
    int bid = blockIdx.x;
    int grp = bid >> 7;
    int rr = bid & 127;
    const int mt = grp * 8 + (rr & 7);
    const int nt = rr >> 3;
    const int m0 = mt * BM, n0 = nt * BN;

    const uint32_t fullb = sbase, emptyb = sbase + 128;
    if (tid == 0) {
        #pragma unroll
        for (int s = 0; s < ST; s++) {
            MBARRIER_INIT(fullb + 16 * s, 1);
            MBARRIER_INIT(emptyb + 16 * s, NWARP);
        }
    }
    __syncthreads();

    const char* srcA = (const char*)g_xa + (size_t)mt * KT * A_BLK;
    const char* srcB = (const char*)g_wb + (size_t)nt * KT * B_BLK;

    if (tid == 0) {
        #pragma unroll
        for (int j = 0; j < 3; j++) {
            MBARRIER_EXPECT_TX(fullb + 16 * j, STAGE);
            BULK_G2S(sbase + 1024 + j * STAGE, srcA + (size_t)j * A_BLK, A_BLK, fullb + 16 * j);
            BULK_G2S(sbase + 1024 + j * STAGE + A_BLK, srcB + (size_t)j * B_BLK, B_BLK, fullb + 16 * j);
        }
    }

    // per-lane ldmatrix components. Row pitch = 128B; lane row-in-16 = rin.
    const int rin = ((lane >> 3) & 1) * 8 + (lane & 7);   // 0..15
    const int kh = lane >> 4;                              // k-half within k16
    const int xr = rin & 7;
    uint32_t off_k[4];
    #pragma unroll
    for (int ks = 0; ks < 4; ks++)
        off_k[ks] = (uint32_t)(((ks * 2 + kh) ^ xr) * 16);
    const uint32_t aBase = (uint32_t)((warp_m * 32 + rin) * 128);
    const uint32_t bBase = (uint32_t)(A_BLK + (warp_n * 64 + rin) * 128);

    uint32_t a[2][2][4], b[2][4][4];
    float acc[2][8][4];
    #pragma unroll
    for (int i = 0; i < 2; i++)
        #pragma unroll
        for (int j = 0; j < 8; j++)
            #pragma unroll
            for (int c = 0; c < 4; c++) acc[i][j][c] = 0.f;

    auto load_frags = [&](int d, uint32_t sa, uint32_t ko) {
        #pragma unroll
        for (int mi = 0; mi < 2; mi++)
            LDMATRIX_X4(a[d][mi][0], a[d][mi][1], a[d][mi][2], a[d][mi][3],
                        sa + aBase + mi * 2048 + ko);
        #pragma unroll
        for (int nj = 0; nj < 4; nj++)
            LDMATRIX_X4(b[d][nj][0], b[d][nj][1], b[d][nj][2], b[d][nj][3],
                        sa + bBase + nj * 2048 + ko);
    };
    auto mma_block = [&](int d) {
        #pragma unroll
        for (int mi = 0; mi < 2; mi++)
            #pragma unroll
            for (int v = 0; v < 8; v++) {
                int nj = v >> 1, tb = v & 1;
                MMA_16816(acc[mi][v],
                          a[d][mi][0], a[d][mi][1], a[d][mi][2], a[d][mi][3],
                          b[d][nj][tb], b[d][nj][tb + 2]);
            }
    };

    // prologue: wait stage 0, load (kt=0, ks=0) into buf 0
    MBARRIER_WAIT_PARITY(fullb, 0);
    load_frags(0, sbase + 1024, off_k[0]);

    int cur = 0;
    #pragma unroll 1
    for (int kt = 0; kt < KT; kt++) {
        const int s = kt & 3;
        const uint32_t sa = sbase + 1024 + s * STAGE;

        // ks=0: prefetch ks1, MMA
        load_frags(cur ^ 1, sa, off_k[1]);
        mma_block(cur);
        cur ^= 1;

        // producer: round-robin across warps — warp (kt&15), lane 0
        if (wid == (kt & 15) && lane == 0) {
            int j = kt + 3;
            if (j < KT) {
                int sj = j & 3;
                if (j >= 4) MBARRIER_WAIT_PARITY(emptyb + 16 * sj, ((j - 4) >> 2) & 1);
                MBARRIER_EXPECT_TX(fullb + 16 * sj, STAGE);
                BULK_G2S(sbase + 1024 + sj * STAGE, srcA + (size_t)j * A_BLK, A_BLK, fullb + 16 * sj);
                BULK_G2S(sbase + 1024 + sj * STAGE + A_BLK, srcB + (size_t)j * B_BLK, B_BLK, fullb + 16 * sj);
            }
        }

        // ks=1: prefetch ks2, MMA
        load_frags(cur ^ 1, sa, off_k[2]);
        mma_block(cur);
        cur ^= 1;

        // ks=2: prefetch ks3, arrive empty (stage fully read after this), MMA
        load_frags(cur ^ 1, sa, off_k[3]);
        if (lane == 0) MBARRIER_ARRIVE(emptyb + 16 * s);
        mma_block(cur);
        cur ^= 1;

        // ks=3: wait next stage, prefetch (kt+1, ks=0), MMA
        if (kt + 1 < KT) {
            const int s2 = (kt + 1) & 3;
            MBARRIER_WAIT_PARITY(fullb + 16 * s2, ((kt + 1) >> 2) & 1);
            load_frags(cur ^ 1, sbase + 1024 + s2 * STAGE, off_k[0]);
        }
        mma_block(cur);
        cur ^= 1;
    }

    // epilogue: scale + bias, float2 stores
    const float scale = __ldg(wscale);
    const int g = lane >> 2, tg = lane & 3;
    #pragma unroll
    for (int mi = 0; mi < 2; mi++) {
        #pragma unroll
        for (int v = 0; v < 8; v++) {
            int col = n0 + warp_n * 64 + v * 8 + tg * 2;
            float2 bb = *reinterpret_cast<const float2*>(bias + col);
            #pragma unroll
            for (int rh = 0; rh < 2; rh++) {
                int row = m0 + warp_m * 32 + mi * 16 + g + rh * 8;
                float2 o;
                o.x = acc[mi][v][rh * 2 + 0] * scale + bb.x;
                o.y = acc[mi][v][rh * 2 + 1] * scale + bb.y;
                *reinterpret_cast<float2*>(out + (size_t)row * NDIM + col) = o;
            }
        }
    }
}

// ------------------------------- launch ------------------------------------
extern "C" void kernel_launch(void* const* d_in, const int* in_sizes, int n_in,
                              void* d_out, int out_size) {
    const float* x     = (const float*)d_in[0];
    const int*   q     = (const int*)d_in[1];
    const int*   zp    = (const int*)d_in[2];
    const float* scale = (const float*)d_in[3];
    const float* bias  = (const float*)d_in[4];
    float* out = (float*)d_out;

    cudaFuncSetAttribute(gemm_kernel, cudaFuncAttributeMaxDynamicSharedMemorySize, SMEM_TOTAL);

    prep_kernel<<<XBLKS + WBLKS, 256>>>(x, q, zp);

    const int grid = (MDIM / BM) * (NDIM / BN);   // 64 * 16 = 1024
    gemm_kernel<<<grid, 512, SMEM_TOTAL>>>(bias, scale, out);
}

// round 9
// speedup vs baseline: 1.0887x; 1.0887x over previous
#include <cuda_runtime.h>
#include <cuda_fp16.h>
#include <cstdint>

// out[8192,4096] = x[8192,4096] @ W[4096,4096]^T,  W = (q - zp)*scale
// fp16 HMMA (mma.sync.m16n8k16, fp32 accum). cp.async.bulk loads from
// prep-tiled pre-swizzled scratch; register ping-pong; 8 warps (64x64 warp
// tile, best LDSM/MMA ratio); BK=128 + 2-stage ring to amortize per-iter
// barrier overhead over 4096 tensor cycles.
#define MDIM 8192
#define KDIM 4096
#define NDIM 4096

static constexpr int BM = 128, BN = 256, BK = 128;
static constexpr int A_BLK = BM * BK * 2;     // 32768 B per (m-tile, k-chunk)
static constexpr int B_BLK = BN * BK * 2;     // 65536 B
static constexpr int STAGE = A_BLK + B_BLK;   // 98304
static constexpr int ST = 2;
static constexpr int KT = KDIM / BK;          // 32
static constexpr int SMEM_TOTAL = 1024 + ST * STAGE;  // 197632

// tiled+swizzled scratch: A: [64 mt][32 kt][32KB], B: [16 nt][32 kt][64KB]
// row r holds a 256B K-slice (128 fp16). 16B unit u stored at
// r*256 + ((u&8) | ((u^r)&7)) * 16  -> conflict-free ldmatrix.
__device__ uint4 g_xa[(size_t)MDIM * KDIM * 2 / 16];
__device__ uint4 g_wb[(size_t)NDIM * KDIM * 2 / 16];

__device__ __forceinline__ uint32_t smem_to_u32(const void* p) {
    uint32_t a;
    asm("{ .reg .u64 t; cvta.to.shared.u64 t, %1; cvt.u32.u64 %0, t; }"
        : "=r"(a) : "l"(p));
    return a;
}

#define MBARRIER_INIT(addr, cnt) \
    asm volatile("mbarrier.init.shared.b64 [%0], %1;" :: "r"((uint32_t)(addr)), "r"((uint32_t)(cnt)) : "memory")
#define MBARRIER_ARRIVE(addr) \
    asm volatile("mbarrier.arrive.shared.b64 _, [%0];" :: "r"((uint32_t)(addr)) : "memory")
#define MBARRIER_EXPECT_TX(addr, bytes) \
    asm volatile("mbarrier.arrive.expect_tx.shared.b64 _, [%0], %1;" :: "r"((uint32_t)(addr)), "r"((uint32_t)(bytes)) : "memory")
#define MBARRIER_WAIT_PARITY(mbar_smem_addr, phase_parity) do { \
    uint32_t _mbar = (uint32_t)(mbar_smem_addr); \
    uint32_t _parity = (uint32_t)(phase_parity); \
    uint32_t _done; \
    asm volatile( \
        "{\n\t.reg .pred p;\n\t" \
        "mbarrier.try_wait.parity.acquire.cta.shared::cta.b64 p, [%1], %2;\n\t" \
        "selp.b32 %0, 1, 0, p;\n\t}" \
        : "=r"(_done) : "r"(_mbar), "r"(_parity) : "memory"); \
    if (!_done) { \
        asm volatile( \
            "{\n\t.reg .pred P1;\n\t" \
            "WAIT_LOOP_%=:\n\t" \
            "mbarrier.try_wait.parity.acquire.cta.shared::cta.b64 P1, [%0], %1, 0x989680;\n\t" \
            "@P1 bra.uni WAIT_DONE_%=;\n\t" \
            "bra.uni WAIT_LOOP_%=;\n\t" \
            "WAIT_DONE_%=:\n\t}" \
            :: "r"(_mbar), "r"(_parity) : "memory"); \
    } \
} while(0)

#define BULK_G2S(dst, src, bytes, mbar) \
    asm volatile("cp.async.bulk.shared::cluster.global.mbarrier::complete_tx::bytes [%0], [%1], %2, [%3];" \
        :: "r"((uint32_t)(dst)), "l"(src), "r"((uint32_t)(bytes)), "r"((uint32_t)(mbar)) : "memory")

#define LDMATRIX_X4(r0, r1, r2, r3, addr) \
    asm volatile("ldmatrix.sync.aligned.m8n8.x4.shared.b16 {%0,%1,%2,%3}, [%4];" \
        : "=r"(r0), "=r"(r1), "=r"(r2), "=r"(r3) : "r"(addr))

#define MMA_16816(c, a0, a1, a2, a3, b0, b1) \
    asm volatile("mma.sync.aligned.m16n8k16.row.col.f32.f16.f16.f32 " \
        "{%0,%1,%2,%3}, {%4,%5,%6,%7}, {%8,%9}, {%0,%1,%2,%3};" \
        : "+f"((c)[0]), "+f"((c)[1]), "+f"((c)[2]), "+f"((c)[3]) \
        : "r"(a0), "r"(a1), "r"(a2), "r"(a3), "r"(b0), "r"(b1))

// ------------------------------- prep kernel -------------------------------
static constexpr int XBLKS = (int)(((size_t)MDIM * KDIM / 8) / 256);  // 16384
static constexpr int WBLKS = (int)(((size_t)NDIM * KDIM / 8) / 256);  // 8192

__device__ __forceinline__ uint32_t swz256(int r, int u) {   // 256B rows, 16 units
    return (uint32_t)r * 256 + (uint32_t)(((u & 8) | ((u ^ r) & 7)) * 16);
}

__global__ void __launch_bounds__(256) prep_kernel(const float* __restrict__ x,
                                                   const int* __restrict__ q,
                                                   const int* __restrict__ zp) {
    if (blockIdx.x < XBLKS) {
        size_t t = (size_t)blockIdx.x * blockDim.x + threadIdx.x;  // one 16B unit
        int m = (int)(t >> 9);
        int k = ((int)t & 511) * 8;
        const float4* src = reinterpret_cast<const float4*>(x + (size_t)m * KDIM + k);
        float4 v0 = src[0], v1 = src[1];
        __half2 h0 = __floats2half2_rn(v0.x, v0.y);
        __half2 h1 = __floats2half2_rn(v0.z, v0.w);
        __half2 h2 = __floats2half2_rn(v1.x, v1.y);
        __half2 h3 = __floats2half2_rn(v1.z, v1.w);
        uint4 o;
        o.x = *reinterpret_cast<uint32_t*>(&h0);
        o.y = *reinterpret_cast<uint32_t*>(&h1);
        o.z = *reinterpret_cast<uint32_t*>(&h2);
        o.w = *reinterpret_cast<uint32_t*>(&h3);
        int mt = m >> 7, r = m & 127, kt = k >> 7, u = (k & 127) >> 3;
        g_xa[((size_t)(mt * KT + kt) * A_BLK + swz256(r, u)) >> 4] = o;
    } else {
        int z = __ldg(zp);
        size_t t = (size_t)(blockIdx.x - XBLKS) * blockDim.x + threadIdx.x;
        int n = (int)(t >> 9);
        int k = ((int)t & 511) * 8;
        const int4* src = reinterpret_cast<const int4*>(q + (size_t)n * KDIM + k);
        int4 q0 = src[0], q1 = src[1];
        __half2 h0 = __floats2half2_rn((float)(q0.x - z), (float)(q0.y - z));
        __half2 h1 = __floats2half2_rn((float)(q0.z - z), (float)(q0.w - z));
        __half2 h2 = __floats2half2_rn((float)(q1.x - z), (float)(q1.y - z));
        __half2 h3 = __floats2half2_rn((float)(q1.z - z), (float)(q1.w - z));
        uint4 o;
        o.x = *reinterpret_cast<uint32_t*>(&h0);
        o.y = *reinterpret_cast<uint32_t*>(&h1);
        o.z = *reinterpret_cast<uint32_t*>(&h2);
        o.w = *reinterpret_cast<uint32_t*>(&h3);
        int nt = n >> 8, r = n & 255, kt = k >> 7, u = (k & 127) >> 3;
        g_wb[((size_t)(nt * KT + kt) * B_BLK + swz256(r, u)) >> 4] = o;
    }
}

// ------------------------------- GEMM --------------------------------------
// CTA 128x256, K-chunk 128 (8 k16 steps). 8 warps: 2(M) x 4(N), tile 64x64.
__global__ void __launch_bounds__(256, 1)
gemm_kernel(const float* __restrict__ bias,
            const float* __restrict__ wscale,
            float* __restrict__ out) {
    extern __shared__ char smem[];
    const uint32_t sbase = smem_to_u32(smem);
    const int tid = threadIdx.x;
    const int lane = tid & 31;
    const int wid = tid >> 5;
    const int warp_m = wid & 1;
    const int warp_n = wid >> 1;

    // CTA swizzle: groups of 8 M-tiles sweep all 16 N-tiles
    int bid = blockIdx.x;
    int grp = bid >> 7;
    int rr = bid & 127;
    const int mt = grp * 8 + (rr & 7);
    const int nt = rr >> 3;
    const int m0 = mt * BM, n0 = nt * BN;

    const uint32_t fullb = sbase, emptyb = sbase + 128;
    if (tid == 0) {
        #pragma unroll
        for (int s = 0; s < ST; s++) {
            MBARRIER_INIT(fullb + 16 * s, 1);
            MBARRIER_INIT(emptyb + 16 * s, 8);
        }
    }
    __syncthreads();

    const char* srcA = (const char*)g_xa + (size_t)mt * KT * A_BLK;
    const char* srcB = (const char*)g_wb + (size_t)nt * KT * B_BLK;

    // prologue: fill chunk 0 only; chunk 1 comes from the iter-0 producer.
    if (tid == 0) {
        MBARRIER_EXPECT_TX(fullb, STAGE);
        BULK_G2S(sbase + 1024, srcA, A_BLK, fullb);
        BULK_G2S(sbase + 1024 + A_BLK, srcB, B_BLK, fullb);
    }

    // per-lane ldmatrix components. Row pitch = 256B; lane row-in-16 = rin.
    const int rin = ((lane >> 3) & 1) * 8 + (lane & 7);   // 0..15
    const int kh = lane >> 4;                              // k-half within k16
    const int xr = rin & 7;
    uint32_t off_k[8];
    #pragma unroll
    for (int ks = 0; ks < 8; ks++) {
        int base = ks * 2 + kh;                            // unit 0..15
        off_k[ks] = (uint32_t)(((base & 8) | ((base ^ xr) & 7)) * 16);
    }
    const uint32_t aBase = (uint32_t)((warp_m * 64 + rin) * 256);
    const uint32_t bBase = (uint32_t)(A_BLK + (warp_n * 64 + rin) * 256);

    uint32_t a[2][4][4], b[2][4][4];
    float acc[4][8][4];
    #pragma unroll
    for (int i = 0; i < 4; i++)
        #pragma unroll
        for (int j = 0; j < 8; j++)
            #pragma unroll
            for (int c = 0; c < 4; c++) acc[i][j][c] = 0.f;

    auto load_frags = [&](int d, uint32_t sa, uint32_t ko) {
        #pragma unroll
        for (int mi = 0; mi < 4; mi++)
            LDMATRIX_X4(a[d][mi][0], a[d][mi][1], a[d][mi][2], a[d][mi][3],
                        sa + aBase + mi * 4096 + ko);
        #pragma unroll
        for (int nj = 0; nj < 4; nj++)
            LDMATRIX_X4(b[d][nj][0], b[d][nj][1], b[d][nj][2], b[d][nj][3],
                        sa + bBase + nj * 4096 + ko);
    };
    auto mma_block = [&](int d) {
        #pragma unroll
        for (int mi = 0; mi < 4; mi++)
            #pragma unroll
            for (int v = 0; v < 8; v++) {
                int nj = v >> 1, tb = v & 1;
                MMA_16816(acc[mi][v],
                          a[d][mi][0], a[d][mi][1], a[d][mi][2], a[d][mi][3],
                          b[d][nj][tb], b[d][nj][tb + 2]);
            }
    };

    // wait chunk 0, load its first fragment set
    MBARRIER_WAIT_PARITY(fullb, 0);
    load_frags(0, sbase + 1024, off_k[0]);

    int cur = 0;
    #pragma unroll 1
    for (int kt = 0; kt < KT; kt++) {
        const int s = kt & 1;
        const uint32_t sa = sbase + 1024 + s * STAGE;

        // ks=0: prefetch ks1, MMA
        load_frags(cur ^ 1, sa, off_k[1]);
        mma_block(cur);
        cur ^= 1;

        // producer (RR warp, lane 0): fill chunk kt+1 into the other stage.
        // That stage's empty was released at iter kt-1 (ks=6) — no same-iter
        // dependency. Chunk j's full phase = (j>>1)&1; empty phase to wait
        // before refilling = ((j-2)>>1)&1 (j>=2).
        if (wid == (kt & 7) && lane == 0) {
            int j = kt + 1;
            if (j < KT) {
                int sj = j & 1;
                if (j >= 2) MBARRIER_WAIT_PARITY(emptyb + 16 * sj, ((j - 2) >> 1) & 1);
                MBARRIER_EXPECT_TX(fullb + 16 * sj, STAGE);
                BULK_G2S(sbase + 1024 + sj * STAGE, srcA + (size_t)j * A_BLK, A_BLK, fullb + 16 * sj);
                BULK_G2S(sbase + 1024 + sj * STAGE + A_BLK, srcB + (size_t)j * B_BLK, B_BLK, fullb + 16 * sj);
            }
        }

        // ks=1..5: prefetch next, MMA
        #pragma unroll
        for (int ks = 1; ks <= 5; ks++) {
            load_frags(cur ^ 1, sa, off_k[ks + 1]);
            mma_block(cur);
            cur ^= 1;
        }

        // ks=6: prefetch ks7 (last read of stage s), arrive empty, MMA
        load_frags(cur ^ 1, sa, off_k[7]);
        if (lane == 0) MBARRIER_ARRIVE(emptyb + 16 * s);
        mma_block(cur);
        cur ^= 1;

        // ks=7: wait next chunk's full, prefetch its ks0, MMA
        if (kt + 1 < KT) {
            const int s2 = (kt + 1) & 1;
            MBARRIER_WAIT_PARITY(fullb + 16 * s2, ((kt + 1) >> 1) & 1);
            load_frags(cur ^ 1, sbase + 1024 + s2 * STAGE, off_k[0]);
        }
        mma_block(cur);
        cur ^= 1;
    }

    // epilogue: scale + bias, float2 stores
    const float scale = __ldg(wscale);
    const int g = lane >> 2, tg = lane & 3;
    #pragma unroll
    for (int mi = 0; mi < 4; mi++) {
        #pragma unroll
        for (int v = 0; v < 8; v++) {
            int col = n0 + warp_n * 64 + v * 8 + tg * 2;
            float2 bb = *reinterpret_cast<const float2*>(bias + col);
            #pragma unroll
            for (int rh = 0; rh < 2; rh++) {
                int row = m0 + warp_m * 64 + mi * 16 + g + rh * 8;
                float2 o;
                o.x = acc[mi][v][rh * 2 + 0] * scale + bb.x;
                o.y = acc[mi][v][rh * 2 + 1] * scale + bb.y;
                *reinterpret_cast<float2*>(out + (size_t)row * NDIM + col) = o;
            }
        }
    }
}

// ------------------------------- launch ------------------------------------
extern "C" void kernel_launch(void* const* d_in, const int* in_sizes, int n_in,
                              void* d_out, int out_size) {
    const float* x     = (const float*)d_in[0];
    const int*   q     = (const int*)d_in[1];
    const int*   zp    = (const int*)d_in[2];
    const float* scale = (const float*)d_in[3];
    const float* bias  = (const float*)d_in[4];
    float* out = (float*)d_out;

    cudaFuncSetAttribute(gemm_kernel, cudaFuncAttributeMaxDynamicSharedMemorySize, SMEM_TOTAL);

    prep_kernel<<<XBLKS + WBLKS, 256>>>(x, q, zp);

    const int grid = (MDIM / BM) * (NDIM / BN);   // 64 * 16 = 1024
    gemm_kernel<<<grid, 256, SMEM_TOTAL>>>(bias, scale, out);
}

// round 10
// speedup vs baseline: 1.1122x; 1.0216x over previous
#include <cuda_runtime.h>
#include <cuda_fp16.h>
#include <cstdint>

// out[8192,4096] = x[8192,4096] @ W[4096,4096]^T,  W = (q - zp)*scale
// fp16 HMMA (mma.sync.m16n8k16, fp32 accum). cp.async.bulk loads from
// prep-tiled pre-swizzled scratch; register ping-pong; BK=64, 4-stage ring
// (R7 config) + peek-ahead full-wait so the TRYWAIT latency hides under MMAs.
#define MDIM 8192
#define KDIM 4096
#define NDIM 4096

static constexpr int BM = 128, BN = 256, BK = 64;
static constexpr int A_BLK = BM * BK * 2;     // 16384 B per (m-tile, k-chunk)
static constexpr int B_BLK = BN * BK * 2;     // 32768 B
static constexpr int STAGE = A_BLK + B_BLK;   // 49152
static constexpr int ST = 4;
static constexpr int KT = KDIM / BK;          // 64
static constexpr int SMEM_TOTAL = 1024 + ST * STAGE;  // 197632

// tiled+swizzled scratch: A: [64 mt][64 kt][16KB], B: [16 nt][64 kt][32KB]
// row r holds its 128B K-slice; 16B unit u at offset r*128 + (u^(r&7))*16.
__device__ uint4 g_xa[(size_t)MDIM * KDIM * 2 / 16];
__device__ uint4 g_wb[(size_t)NDIM * KDIM * 2 / 16];

__device__ __forceinline__ uint32_t smem_to_u32(const void* p) {
    uint32_t a;
    asm("{ .reg .u64 t; cvta.to.shared.u64 t, %1; cvt.u32.u64 %0, t; }"
        : "=r"(a) : "l"(p));
    return a;
}

#define MBARRIER_INIT(addr, cnt) \
    asm volatile("mbarrier.init.shared.b64 [%0], %1;" :: "r"((uint32_t)(addr)), "r"((uint32_t)(cnt)) : "memory")
#define MBARRIER_ARRIVE(addr) \
    asm volatile("mbarrier.arrive.shared.b64 _, [%0];" :: "r"((uint32_t)(addr)) : "memory")
#define MBARRIER_EXPECT_TX(addr, bytes) \
    asm volatile("mbarrier.arrive.expect_tx.shared.b64 _, [%0], %1;" :: "r"((uint32_t)(addr)), "r"((uint32_t)(bytes)) : "memory")

// single non-blocking probe; returns 1 if phase complete (with acquire)
__device__ __forceinline__ uint32_t mbar_try_once(uint32_t mbar, uint32_t parity) {
    uint32_t done;
    asm volatile(
        "{\n\t.reg .pred p;\n\t"
        "mbarrier.try_wait.parity.acquire.cta.shared::cta.b64 p, [%1], %2;\n\t"
        "selp.b32 %0, 1, 0, p;\n\t}"
        : "=r"(done) : "r"(mbar), "r"(parity) : "memory");
    return done;
}

#define MBARRIER_WAIT_PARITY(mbar_smem_addr, phase_parity) do { \
    uint32_t _mbar = (uint32_t)(mbar_smem_addr); \
    uint32_t _parity = (uint32_t)(phase_parity); \
    uint32_t _done; \
    asm volatile( \
        "{\n\t.reg .pred p;\n\t" \
        "mbarrier.try_wait.parity.acquire.cta.shared::cta.b64 p, [%1], %2;\n\t" \
        "selp.b32 %0, 1, 0, p;\n\t}" \
        : "=r"(_done) : "r"(_mbar), "r"(_parity) : "memory"); \
    if (!_done) { \
        asm volatile( \
            "{\n\t.reg .pred P1;\n\t" \
            "WAIT_LOOP_%=:\n\t" \
            "mbarrier.try_wait.parity.acquire.cta.shared::cta.b64 P1, [%0], %1, 0x989680;\n\t" \
            "@P1 bra.uni WAIT_DONE_%=;\n\t" \
            "bra.uni WAIT_LOOP_%=;\n\t" \
            "WAIT_DONE_%=:\n\t}" \
            :: "r"(_mbar), "r"(_parity) : "memory"); \
    } \
} while(0)

#define BULK_G2S(dst, src, bytes, mbar) \
    asm volatile("cp.async.bulk.shared::cluster.global.mbarrier::complete_tx::bytes [%0], [%1], %2, [%3];" \
        :: "r"((uint32_t)(dst)), "l"(src), "r"((uint32_t)(bytes)), "r"((uint32_t)(mbar)) : "memory")

#define LDMATRIX_X4(r0, r1, r2, r3, addr) \
    asm volatile("ldmatrix.sync.aligned.m8n8.x4.shared.b16 {%0,%1,%2,%3}, [%4];" \
        : "=r"(r0), "=r"(r1), "=r"(r2), "=r"(r3) : "r"(addr))

#define MMA_16816(c, a0, a1, a2, a3, b0, b1) \
    asm volatile("mma.sync.aligned.m16n8k16.row.col.f32.f16.f16.f32 " \
        "{%0,%1,%2,%3}, {%4,%5,%6,%7}, {%8,%9}, {%0,%1,%2,%3};" \
        : "+f"((c)[0]), "+f"((c)[1]), "+f"((c)[2]), "+f"((c)[3]) \
        : "r"(a0), "r"(a1), "r"(a2), "r"(a3), "r"(b0), "r"(b1))

// ------------------------------- prep kernel -------------------------------
static constexpr int XBLKS = (int)(((size_t)MDIM * KDIM / 8) / 256);  // 16384
static constexpr int WBLKS = (int)(((size_t)NDIM * KDIM / 8) / 256);  // 8192

__global__ void __launch_bounds__(256) prep_kernel(const float* __restrict__ x,
                                                   const int* __restrict__ q,
                                                   const int* __restrict__ zp) {
    if (blockIdx.x < XBLKS) {
        size_t t = (size_t)blockIdx.x * blockDim.x + threadIdx.x;  // one 16B unit
        int m = (int)(t >> 9);
        int k = ((int)t & 511) * 8;
        const float4* src = reinterpret_cast<const float4*>(x + (size_t)m * KDIM + k);
        float4 v0 = src[0], v1 = src[1];
        __half2 h0 = __floats2half2_rn(v0.x, v0.y);
        __half2 h1 = __floats2half2_rn(v0.z, v0.w);
        __half2 h2 = __floats2half2_rn(v1.x, v1.y);
        __half2 h3 = __floats2half2_rn(v1.z, v1.w);
        uint4 o;
        o.x = *reinterpret_cast<uint32_t*>(&h0);
        o.y = *reinterpret_cast<uint32_t*>(&h1);
        o.z = *reinterpret_cast<uint32_t*>(&h2);
        o.w = *reinterpret_cast<uint32_t*>(&h3);
        int mt = m >> 7, r = m & 127, kt = k >> 6, kc8 = (k & 63) >> 3;
        uint32_t off = (uint32_t)r * 128 + (uint32_t)((kc8 ^ (r & 7)) * 16);
        g_xa[((size_t)(mt * KT + kt) * A_BLK + off) >> 4] = o;
    } else {
        int z = __ldg(zp);
        size_t t = (size_t)(blockIdx.x - XBLKS) * blockDim.x + threadIdx.x;
        int n = (int)(t >> 9);
        int k = ((int)t & 511) * 8;
        const int4* src = reinterpret_cast<const int4*>(q + (size_t)n * KDIM + k);
        int4 q0 = src[0], q1 = src[1];
        __half2 h0 = __floats2half2_rn((float)(q0.x - z), (float)(q0.y - z));
        __half2 h1 = __floats2half2_rn((float)(q0.z - z), (float)(q0.w - z));
        __half2 h2 = __floats2half2_rn((float)(q1.x - z), (float)(q1.y - z));
        __half2 h3 = __floats2half2_rn((float)(q1.z - z), (float)(q1.w - z));
        uint4 o;
        o.x = *reinterpret_cast<uint32_t*>(&h0);
        o.y = *reinterpret_cast<uint32_t*>(&h1);
        o.z = *reinterpret_cast<uint32_t*>(&h2);
        o.w = *reinterpret_cast<uint32_t*>(&h3);
        int nt = n >> 8, r = n & 255, kt = k >> 6, kc8 = (k & 63) >> 3;
        uint32_t off = (uint32_t)r * 128 + (uint32_t)((kc8 ^ (r & 7)) * 16);
        g_wb[((size_t)(nt * KT + kt) * B_BLK + off) >> 4] = o;
    }
}

// ------------------------------- GEMM --------------------------------------
// CTA 128x256, K-chunk 64. 8 warps: 2(M) x 4(N), warp tile 64x64.
__global__ void __launch_bounds__(256, 1)
gemm_kernel(const float* __restrict__ bias,
            const float* __restrict__ wscale,
            float* __restrict__ out) {
    extern __shared__ char smem[];
    const uint32_t sbase = smem_to_u32(smem);
    const int tid = threadIdx.x;
    const int lane = tid & 31;
    const int wid = tid >> 5;
    const int warp_m = wid & 1;
    const int warp_n = wid >> 1;

    // CTA swizzle: groups of 8 M-tiles sweep all 16 N-tiles
    int bid = blockIdx.x;
    int grp = bid >> 7;
    int rr = bid & 127;
    const int mt = grp * 8 + (rr & 7);
    const int nt = rr >> 3;
    const int m0 = mt * BM, n0 = nt * BN;

    const uint32_t fullb = sbase, emptyb = sbase + 128;
    if (tid == 0) {
        #pragma unroll
        for (int s = 0; s < ST; s++) {
            MBARRIER_INIT(fullb + 16 * s, 1);
            MBARRIER_INIT(emptyb + 16 * s, 8);
        }
    }
    __syncthreads();

    const char* srcA = (const char*)g_xa + (size_t)mt * KT * A_BLK;
    const char* srcB = (const char*)g_wb + (size_t)nt * KT * B_BLK;

    if (tid == 0) {
        #pragma unroll
        for (int j = 0; j < 3; j++) {
            MBARRIER_EXPECT_TX(fullb + 16 * j, STAGE);
            BULK_G2S(sbase + 1024 + j * STAGE, srcA + (size_t)j * A_BLK, A_BLK, fullb + 16 * j);
            BULK_G2S(sbase + 1024 + j * STAGE + A_BLK, srcB + (size_t)j * B_BLK, B_BLK, fullb + 16 * j);
        }
    }

    // per-lane ldmatrix components. Row pitch = 128B; lane row-in-16 = rin.
    const int rin = ((lane >> 3) & 1) * 8 + (lane & 7);   // 0..15
    const int kh = lane >> 4;                              // k-half within k16
    const int xr = rin & 7;
    uint32_t off_k[4];
    #pragma unroll
    for (int ks = 0; ks < 4; ks++)
        off_k[ks] = (uint32_t)(((ks * 2 + kh) ^ xr) * 16);
    const uint32_t aBase = (uint32_t)((warp_m * 64 + rin) * 128);
    const uint32_t bBase = (uint32_t)(A_BLK + (warp_n * 64 + rin) * 128);

    uint32_t a[2][4][4], b[2][4][4];
    float acc[4][8][4];
    #pragma unroll
    for (int i = 0; i < 4; i++)
        #pragma unroll
        for (int j = 0; j < 8; j++)
            #pragma unroll
            for (int c = 0; c < 4; c++) acc[i][j][c] = 0.f;

    auto load_frags = [&](int d, uint32_t sa, uint32_t ko) {
        #pragma unroll
        for (int mi = 0; mi < 4; mi++)
            LDMATRIX_X4(a[d][mi][0], a[d][mi][1], a[d][mi][2], a[d][mi][3],
                        sa + aBase + mi * 2048 + ko);
        #pragma unroll
        for (int nj = 0; nj < 4; nj++)
            LDMATRIX_X4(b[d][nj][0], b[d][nj][1], b[d][nj][2], b[d][nj][3],
                        sa + bBase + nj * 2048 + ko);
    };
    auto mma_block = [&](int d) {
        #pragma unroll
        for (int mi = 0; mi < 4; mi++)
            #pragma unroll
            for (int v = 0; v < 8; v++) {
                int nj = v >> 1, tb = v & 1;
                MMA_16816(acc[mi][v],
                          a[d][mi][0], a[d][mi][1], a[d][mi][2], a[d][mi][3],
                          b[d][nj][tb], b[d][nj][tb + 2]);
            }
    };

    // prologue: wait stage 0, load (kt=0, ks=0) into buf 0
    MBARRIER_WAIT_PARITY(fullb, 0);
    load_frags(0, sbase + 1024, off_k[0]);

    int cur = 0;
    #pragma unroll 1
    for (int kt = 0; kt < KT; kt++) {
        const int s = kt & 3;
        const uint32_t sa = sbase + 1024 + s * STAGE;
        const int s2 = (kt + 1) & 3;
        const uint32_t ph2 = (uint32_t)(((kt + 1) >> 2) & 1);

        // ks=0: prefetch ks1, MMA
        load_frags(cur ^ 1, sa, off_k[1]);
        mma_block(cur);
        cur ^= 1;

        // producer: round-robin across warps — warp (kt&7), lane 0
        if (wid == (kt & 7) && lane == 0) {
            int j = kt + 3;
            if (j < KT) {
                int sj = j & 3;
                if (j >= 4) MBARRIER_WAIT_PARITY(emptyb + 16 * sj, ((j - 4) >> 2) & 1);
                MBARRIER_EXPECT_TX(fullb + 16 * sj, STAGE);
                BULK_G2S(sbase + 1024 + sj * STAGE, srcA + (size_t)j * A_BLK, A_BLK, fullb + 16 * sj);
                BULK_G2S(sbase + 1024 + sj * STAGE + A_BLK, srcB + (size_t)j * B_BLK, B_BLK, fullb + 16 * sj);
            }
        }

        // ks=1: prefetch ks2, MMA
        load_frags(cur ^ 1, sa, off_k[2]);
        mma_block(cur);
        cur ^= 1;

        // ks=2: prefetch ks3, arrive empty, PEEK next stage's full, MMA.
        // The try_wait's ~90cyc latency overlaps this 256-cyc MMA block.
        load_frags(cur ^ 1, sa, off_k[3]);
        if (lane == 0) MBARRIER_ARRIVE(emptyb + 16 * s);
        uint32_t nextReady = 0;
        if (kt + 1 < KT) nextReady = mbar_try_once(fullb + 16 * s2, ph2);
        mma_block(cur);
        cur ^= 1;

        // ks=3: blocking wait only if the peek missed; prefetch (kt+1,ks0), MMA
        if (kt + 1 < KT) {
            if (!nextReady) MBARRIER_WAIT_PARITY(fullb + 16 * s2, ph2);
            load_frags(cur ^ 1, sbase + 1024 + s2 * STAGE, off_k[0]);
        }
        mma_block(cur);
        cur ^= 1;
    }

    // epilogue: scale + bias, float2 stores
    const float scale = __ldg(wscale);
    const int g = lane >> 2, tg = lane & 3;
    #pragma unroll
    for (int mi = 0; mi < 4; mi++) {
        #pragma unroll
        for (int v = 0; v < 8; v++) {
            int col = n0 + warp_n * 64 + v * 8 + tg * 2;
            float2 bb = *reinterpret_cast<const float2*>(bias + col);
            #pragma unroll
            for (int rh = 0; rh < 2; rh++) {
                int row = m0 + warp_m * 64 + mi * 16 + g + rh * 8;
                float2 o;
                o.x = acc[mi][v][rh * 2 + 0] * scale + bb.x;
                o.y = acc[mi][v][rh * 2 + 1] * scale + bb.y;
                *reinterpret_cast<float2*>(out + (size_t)row * NDIM + col) = o;
            }
        }
    }
}

// ------------------------------- launch ------------------------------------
extern "C" void kernel_launch(void* const* d_in, const int* in_sizes, int n_in,
                              void* d_out, int out_size) {
    const float* x     = (const float*)d_in[0];
    const int*   q     = (const int*)d_in[1];
    const int*   zp    = (const int*)d_in[2];
    const float* scale = (const float*)d_in[3];
    const float* bias  = (const float*)d_in[4];
    float* out = (float*)d_out;

    cudaFuncSetAttribute(gemm_kernel, cudaFuncAttributeMaxDynamicSharedMemorySize, SMEM_TOTAL);

    prep_kernel<<<XBLKS + WBLKS, 256>>>(x, q, zp);

    const int grid = (MDIM / BM) * (NDIM / BN);   // 64 * 16 = 1024
    gemm_kernel<<<grid, 256, SMEM_TOTAL>>>(bias, scale, out);
}